// round 16
// baseline (speedup 1.0000x reference)
#include <cuda_runtime.h>
#include <cuda_bf16.h>
#include <cuda_fp16.h>
#include <cstdint>
#include <math.h>

#define B_   2
#define S_   2048
#define HID_ 2048
#define NH_  16
#define NKV_ 4
#define D_   128
#define GK   2048

typedef __nv_bfloat16 bf16;

// ---------------------------------------------------------------------------
// Device globals
// ---------------------------------------------------------------------------
__device__ bf16 g_ahi[(size_t)B_ * S_ * HID_];
__device__ bf16 g_alo[(size_t)B_ * S_ * HID_];
// W arena rows 0..2047 = Wq, 2048..2559 = Wk, 2560..3071 = Wv
__device__ bf16 g_whi[6291456];
__device__ bf16 g_wlo[6291456];

__device__ bf16 g_qhi[(size_t)B_ * NH_ * S_ * D_];
__device__ bf16 g_qlo[(size_t)B_ * NH_ * S_ * D_];
__device__ bf16 g_khi[(size_t)B_ * NKV_ * S_ * D_];
__device__ bf16 g_klo[(size_t)B_ * NKV_ * S_ * D_];
__device__ __half g_vthi[(size_t)B_ * NKV_ * D_ * S_];  // [b][kvh][d][s]
__device__ __half g_vtlo[(size_t)B_ * NKV_ * D_ * S_];

__device__ float2 g_rope[S_ * 64];
__device__ int    g_fwork;          // fused work-steal counter (reset in prep)
__device__ int    g_flag[768];      // gemm tile ready flags [nt*32 + mtile]

// Work queue: [0,256) KV tiles | [256,768) Q tiles | [768,1280) attention
#define N_FWORK 1280

struct FalseT { static constexpr bool value = false; };
struct TrueT  { static constexpr bool value = true;  };

// ---------------------------------------------------------------------------
// Helpers
// ---------------------------------------------------------------------------
#define MMA_BF16(C, A, b0v, b1v)                                              \
    asm volatile("mma.sync.aligned.m16n8k16.row.col.f32.bf16.bf16.f32 "       \
                 "{%0,%1,%2,%3}, {%4,%5,%6,%7}, {%8,%9}, {%0,%1,%2,%3};"      \
                 : "+f"((C)[0]), "+f"((C)[1]), "+f"((C)[2]), "+f"((C)[3])     \
                 : "r"((A)[0]), "r"((A)[1]), "r"((A)[2]), "r"((A)[3]),        \
                   "r"(b0v), "r"(b1v))

#define MMA_FP16(C, A, b0v, b1v)                                              \
    asm volatile("mma.sync.aligned.m16n8k16.row.col.f32.f16.f16.f32 "         \
                 "{%0,%1,%2,%3}, {%4,%5,%6,%7}, {%8,%9}, {%0,%1,%2,%3};"      \
                 : "+f"((C)[0]), "+f"((C)[1]), "+f"((C)[2]), "+f"((C)[3])     \
                 : "r"((A)[0]), "r"((A)[1]), "r"((A)[2]), "r"((A)[3]),        \
                   "r"(b0v), "r"(b1v))

#define LDSM_X4(R0, R1, R2, R3, ADDR)                                         \
    asm volatile("ldmatrix.sync.aligned.m8n8.x4.shared.b16 {%0,%1,%2,%3}, [%4];" \
                 : "=r"(R0), "=r"(R1), "=r"(R2), "=r"(R3) : "r"(ADDR))

#define CP16(sa, ga) \
    asm volatile("cp.async.cg.shared.global [%0], [%1], 16;" :: "r"(sa), "l"(ga) : "memory")
#define CPCOMMIT() asm volatile("cp.async.commit_group;" ::: "memory")
#define CPWAIT1()  asm volatile("cp.async.wait_group 1;" ::: "memory")
#define CPWAIT0()  asm volatile("cp.async.wait_group 0;" ::: "memory")

#define PACK_F16(dst, xe, xo) \
    asm("cvt.rn.f16x2.f32 %0, %1, %2;" : "=r"(dst) : "f"(xo), "f"(xe))

__device__ __forceinline__ float ex2f(float x) {
    float r;
    asm("ex2.approx.f32 %0, %1;" : "=f"(r) : "f"(x));
    return r;
}

__device__ __forceinline__ uint32_t smem_to_u32(const void* p) {
    uint32_t a;
    asm("{ .reg .u64 t; cvta.to.shared.u64 t, %1; cvt.u32.u64 %0, t; }" : "=r"(a) : "l"(p));
    return a;
}

__device__ __forceinline__ void spin_flag(const int* f) {
    while (*(volatile const int*)f == 0) {}
}

__device__ __forceinline__ void split_pack(float xe, float xo,
                                           uint32_t& hi, uint32_t& lo) {
    bf16 he = __float2bfloat16_rn(xe);
    bf16 ho = __float2bfloat16_rn(xo);
    float re = xe - __bfloat162float(he);
    float ro = xo - __bfloat162float(ho);
    asm("cvt.rn.bf16x2.f32 %0, %1, %2;" : "=r"(hi) : "f"(__bfloat162float(ho)), "f"(__bfloat162float(he)));
    asm("cvt.rn.bf16x2.f32 %0, %1, %2;" : "=r"(lo) : "f"(ro), "f"(re));
}

// ---------------------------------------------------------------------------
// Fused prep: splits + rope table + counter/flag resets.
// ---------------------------------------------------------------------------
#define PREP_SPLIT 1835008
#define PREP_THREADS 1966080

__global__ __launch_bounds__(256) void prep_all(
    const float4* __restrict__ hs, const float4* __restrict__ Wq,
    const float4* __restrict__ Wk, const float4* __restrict__ Wv,
    uint4* __restrict__ ahi, uint4* __restrict__ alo,
    uint4* __restrict__ whi, uint4* __restrict__ wlo,
    float2* __restrict__ rtab)
{
    int i = blockIdx.x * 256 + threadIdx.x;
    if (i >= PREP_THREADS) return;
    if (i == 0) g_fwork = 0;
    if (i < 768) g_flag[i] = 0;

    if (i >= PREP_SPLIT) {            // rope table
        int idx = i - PREP_SPLIT;     // < 131072
        int d = idx & 63, s = idx >> 6;
        float e2   = (float)(2 * d) * (1.0f / 128.0f);
        float invf = (float)exp(-(double)e2 * 13.815510557964274);
        float ang  = (float)s * invf;
        float sn, cs;
        sincosf(ang, &sn, &cs);
        rtab[idx] = make_float2(cs, sn);
        return;
    }

    const float4* src;
    uint4 *dh, *dl;
    int j;
    if (i < 1048576)      { src = hs; j = i;           dh = ahi;          dl = alo;          }
    else if (i < 1572864) { src = Wq; j = i - 1048576; dh = whi;          dl = wlo;          }
    else if (i < 1703936) { src = Wk; j = i - 1572864; dh = whi + 524288; dl = wlo + 524288; }
    else                  { src = Wv; j = i - 1703936; dh = whi + 655360; dl = wlo + 655360; }

    float4 a = src[2 * j], b = src[2 * j + 1];
    uint32_t h[4], l[4];
    split_pack(a.x, a.y, h[0], l[0]);
    split_pack(a.z, a.w, h[1], l[1]);
    split_pack(b.x, b.y, h[2], l[2]);
    split_pack(b.z, b.w, h[3], l[3]);
    dh[j] = make_uint4(h[0], h[1], h[2], h[3]);
    dl[j] = make_uint4(l[0], l[1], l[2], l[3]);
}

// ---------------------------------------------------------------------------
// Fused persistent kernel: gemm tiles then attention items, one work queue.
// 304 CTAs x 256 threads, smem 106496 (2 CTAs/SM).
// ---------------------------------------------------------------------------
#define GBUF 40960
#define KBUF 34816
#define VOFF 69632
#define FUSED_SMEM 106496

__global__ __launch_bounds__(256, 2) void fused_hmma(
    const bf16* __restrict__ Ahi, const bf16* __restrict__ Alo,
    const bf16* __restrict__ WhiA, const bf16* __restrict__ WloA,
    const float* __restrict__ bq, const float* __restrict__ bk,
    const float* __restrict__ bv, const float2* __restrict__ rtab,
    bf16* __restrict__ Qhi, bf16* __restrict__ Qlo,
    bf16* __restrict__ Khi, bf16* __restrict__ Klo,
    __half* __restrict__ Vthi, __half* __restrict__ Vtlo,
    float* __restrict__ out)
{
    extern __shared__ char sm_[];
    __shared__ int s_item;
    const uint32_t sbase = smem_to_u32(sm_);

    const int t    = threadIdx.x;
    const int wid  = t >> 5;
    const int lane = t & 31;
    const int g    = lane >> 2;
    const int tq   = lane & 3;

    const int a_row  = lane & 15;
    const int a_coff = (lane >> 4) * 16;
    const int b_row  = (lane & 7) + ((lane >> 4) & 1) * 8;
    const int b_coff = ((lane >> 3) & 1) * 16;

    const float NEGBIG = -3.402823466e38f;

    while (true) {
        __syncthreads();
        if (t == 0) s_item = atomicAdd(&g_fwork, 1);
        __syncthreads();
        const int w = s_item;
        if (w >= N_FWORK) break;

        if (w < 768) {
            // =========================== GEMM tile ===========================
            int nt, mtile;
            if (w < 256) { nt = 16 + (w & 7); mtile = w >> 3; }
            else {
                int qi = w - 256;
                nt = qi & 15;
                int idx = qi >> 4;
                mtile = ((idx & 1) << 4) + (15 - (idx >> 1));
            }
            const int m0 = mtile << 7;
            const int wrow0 = nt << 7;
            const int wy = wid >> 1;
            const int wx = wid & 1;

            const float* bias_l; int n0l, Hn, mode;
            bf16 *Ohi, *Olo;
            if (nt < 16)      { bias_l = bq; n0l = nt << 7;        Hn = NH_;  mode = 1; Ohi = Qhi;  Olo = Qlo;  }
            else if (nt < 20) { bias_l = bk; n0l = (nt - 16) << 7; Hn = NKV_; mode = 1; Ohi = Khi;  Olo = Klo;  }
            else              { bias_l = bv; n0l = (nt - 20) << 7; Hn = NKV_; mode = 0; Ohi = (bf16*)Vthi; Olo = (bf16*)Vtlo; }

            const float qsc = (nt < 16) ? (0.08838834764831845f * 1.4426950408889634f) : 1.0f;

            float c[2][8][4];
#pragma unroll
            for (int mi = 0; mi < 2; mi++)
#pragma unroll
                for (int ni = 0; ni < 8; ni++)
#pragma unroll
                    for (int e = 0; e < 4; e++) c[mi][ni][e] = 0.f;

            // prefetch chunk 0
            {
                const uint32_t sb = sbase;
#pragma unroll
                for (int rep = 0; rep < 2; rep++) {
                    int i = t + rep * 256;
                    int r = i >> 2, cc = i & 3;
                    uint32_t so = (uint32_t)((r * 40 + cc * 8) * 2);
                    size_t goA = (size_t)(m0 + r) * GK + cc * 8;
                    size_t goW = (size_t)(wrow0 + r) * GK + cc * 8;
                    CP16(sb +     0 + so, Ahi  + goA);
                    CP16(sb + 10240 + so, Alo  + goA);
                    CP16(sb + 20480 + so, WhiA + goW);
                    CP16(sb + 30720 + so, WloA + goW);
                }
                CPCOMMIT();
            }

            for (int ch = 0; ch < GK / 32; ch++) {
                CPWAIT0();
                __syncthreads();
                if (ch < GK / 32 - 1) {
                    const int kc = (ch + 1) * 32;
                    const uint32_t sb = sbase + ((ch + 1) & 1) * GBUF;
#pragma unroll
                    for (int rep = 0; rep < 2; rep++) {
                        int i = t + rep * 256;
                        int r = i >> 2, cc = i & 3;
                        uint32_t so = (uint32_t)((r * 40 + cc * 8) * 2);
                        size_t goA = (size_t)(m0 + r) * GK + kc + cc * 8;
                        size_t goW = (size_t)(wrow0 + r) * GK + kc + cc * 8;
                        CP16(sb +     0 + so, Ahi  + goA);
                        CP16(sb + 10240 + so, Alo  + goA);
                        CP16(sb + 20480 + so, WhiA + goW);
                        CP16(sb + 30720 + so, WloA + goW);
                    }
                    CPCOMMIT();
                }

                const uint32_t bufb = sbase + (ch & 1) * GBUF;

#pragma unroll
                for (int ks = 0; ks < 2; ks++) {
                    uint32_t ah[2][4], al[2][4];
#pragma unroll
                    for (int mi = 0; mi < 2; mi++) {
                        uint32_t ra = bufb + (uint32_t)((wy * 32 + mi * 16 + a_row) * 80 + ks * 32 + a_coff);
                        LDSM_X4(ah[mi][0], ah[mi][1], ah[mi][2], ah[mi][3], ra);
                        LDSM_X4(al[mi][0], al[mi][1], al[mi][2], al[mi][3], ra + 10240u);
                    }
#pragma unroll
                    for (int gj = 0; gj < 4; gj++) {
                        int n0 = wx * 32 + (gj & 1) * 16 + (gj >> 1) * 64;
                        uint32_t rb = bufb + 20480u + (uint32_t)((n0 + b_row) * 80 + ks * 32 + b_coff);
                        uint32_t h0, h1, h2, h3, l0, l1, l2, l3;
                        LDSM_X4(h0, h1, h2, h3, rb);
                        LDSM_X4(l0, l1, l2, l3, rb + 10240u);
                        int ni = gj * 2;
#pragma unroll
                        for (int mi = 0; mi < 2; mi++) {
                            MMA_BF16(c[mi][ni], ah[mi], h0, h1);
                            MMA_BF16(c[mi][ni], ah[mi], l0, l1);
                            MMA_BF16(c[mi][ni], al[mi], h0, h1);
                            MMA_BF16(c[mi][ni + 1], ah[mi], h2, h3);
                            MMA_BF16(c[mi][ni + 1], ah[mi], l2, l3);
                            MMA_BF16(c[mi][ni + 1], al[mi], h2, h3);
                        }
                    }
                }
            }

            const int h = n0l >> 7;
            const int wy32 = wy * 32;

            if (mode == 1) {
                __syncthreads();
                uint32_t* stageh = (uint32_t*)sm_;
                uint32_t* stagel = (uint32_t*)(sm_ + 34816);
#pragma unroll
                for (int mi = 0; mi < 2; mi++) {
#pragma unroll
                    for (int half = 0; half < 2; half++) {
                        int srl = wy32 + mi * 16 + g + half * 8;
                        int rr  = m0 + srl;
                        int eo  = half * 2;
                        int sr  = rr & (S_ - 1);
#pragma unroll
                        for (int ni = 0; ni < 4; ni++) {
                            int d1 = wx * 32 + ni * 8 + tq * 2;
                            float x1a = c[mi][ni][eo]         + bias_l[n0l + d1];
                            float x1b = c[mi][ni][eo + 1]     + bias_l[n0l + d1 + 1];
                            float x2a = c[mi][ni + 4][eo]     + bias_l[n0l + d1 + 64];
                            float x2b = c[mi][ni + 4][eo + 1] + bias_l[n0l + d1 + 65];
                            float2 ca = rtab[sr * 64 + d1];
                            float2 cb = rtab[sr * 64 + d1 + 1];
                            float o1a = (x1a * ca.x - x2a * ca.y) * qsc;
                            float o2a = (x2a * ca.x + x1a * ca.y) * qsc;
                            float o1b = (x1b * cb.x - x2b * cb.y) * qsc;
                            float o2b = (x2b * cb.x + x1b * cb.y) * qsc;
                            uint32_t ph, pl;
                            split_pack(o1a, o1b, ph, pl);
                            stageh[srl * 68 + (d1 >> 1)] = ph;
                            stagel[srl * 68 + (d1 >> 1)] = pl;
                            split_pack(o2a, o2b, ph, pl);
                            stageh[srl * 68 + ((d1 + 64) >> 1)] = ph;
                            stagel[srl * 68 + ((d1 + 64) >> 1)] = pl;
                        }
                    }
                }
                __syncthreads();
                const int bb  = m0 >> 11;
                const int sr0 = m0 & (S_ - 1);
                const uint4* sh4 = (const uint4*)stageh;
                const uint4* sl4 = (const uint4*)stagel;
                uint4* O4h = (uint4*)Ohi;
                uint4* O4l = (uint4*)Olo;
                for (int idx = t; idx < 128 * 16; idx += 256) {
                    int r = idx >> 4, cc = idx & 15;
                    uint4 vh = sh4[r * 17 + cc];
                    uint4 vl = sl4[r * 17 + cc];
                    size_t off = ((size_t)(bb * Hn + h) * S_ + sr0 + r) * 16 + cc;
                    O4h[off] = vh;
                    O4l[off] = vl;
                }
            } else {
                __syncthreads();
                __half* stageh = (__half*)sm_;
                __half* stagel = (__half*)(sm_ + 34816);
#pragma unroll
                for (int mi = 0; mi < 2; mi++) {
#pragma unroll
                    for (int half = 0; half < 2; half++) {
                        int srl = wy32 + mi * 16 + g + half * 8;
                        int eo = half * 2;
#pragma unroll
                        for (int ni = 0; ni < 8; ni++) {
                            int d = wx * 32 + (ni & 3) * 8 + (ni >> 2) * 64 + tq * 2;
#pragma unroll
                            for (int e = 0; e < 2; e++) {
                                float x = c[mi][ni][eo + e] + bias_l[n0l + d + e];
                                __half hv = __float2half_rn(x);
                                stageh[(d + e) * 136 + srl] = hv;
                                stagel[(d + e) * 136 + srl] = __float2half_rn(x - __half2float(hv));
                            }
                        }
                    }
                }
                __syncthreads();
                const int bb = m0 >> 11;
                const int sr0 = m0 & (S_ - 1);
                const uint4* sh4 = (const uint4*)stageh;
                const uint4* sl4 = (const uint4*)stagel;
                __half* Vh = (__half*)Ohi;
                __half* Vl = (__half*)Olo;
                for (int idx = t; idx < 128 * 16; idx += 256) {
                    int r = idx >> 4, cc = idx & 15;
                    uint4 vh = sh4[r * 17 + cc];
                    uint4 vl = sl4[r * 17 + cc];
                    size_t off = ((size_t)(bb * Hn + h) * D_ + r) * S_ + sr0 + cc * 8;
                    *(uint4*)(Vh + off) = vh;
                    *(uint4*)(Vl + off) = vl;
                }
            }

            // publish: release chain (fence per thread, barrier, flag by t0)
            __threadfence();
            __syncthreads();
            if (t == 0) atomicExch(&g_flag[nt * 32 + mtile], 1);

        } else {
            // ========================= Attention item ========================
            const int aw   = w - 768;            // [0,512)
            const int iblk = 15 - (aw >> 5);     // heavy first
            const int h    = aw & 15;
            const int b    = (aw >> 4) & 1;
            const int q0   = iblk << 7;          // q-tile 128
            const int kvh  = h >> 2;

            const int qflag = h * 32 + (b << 4) + iblk;
            const int kfb   = (16 + kvh) * 32 + (b << 4);
            const int vfb   = (20 + kvh) * 32 + (b << 4);

            const uint4* gkh = (const uint4*)(Khi + ((size_t)(b * NKV_ + kvh) * S_) * D_);
            const uint4* gkl = (const uint4*)(Klo + ((size_t)(b * NKV_ + kvh) * S_) * D_);
            const __half* gvh_base = Vthi + (size_t)(b * NKV_ + kvh) * D_ * S_;
            const __half* gvl_base = Vtlo + (size_t)(b * NKV_ + kvh) * D_ * S_;

            const int ntiles = 2 * iblk + 2;

            // dependency: own Q tile + first K tile
            spin_flag(&g_flag[qflag]);
            spin_flag(&g_flag[kfb]);

            // prologue: prefetch K tile 0
            {
                const uint32_t sb = sbase;
#pragma unroll
                for (int rep = 0; rep < 4; rep++) {
                    int i = t + rep * 256;
                    int r = i >> 4, cc = i & 15;
                    uint32_t so = (uint32_t)((r * 17 + cc) * 16);
                    CP16(sb +         so, gkh + (size_t)r * 16 + cc);
                    CP16(sb + 17408 + so, gkl + (size_t)r * 16 + cc);
                }
                CPCOMMIT();
            }

            // Q fragments (L2 loads — bypass L1 since Q was written this launch)
            const uint32_t* qbh = (const uint32_t*)(Qhi + ((size_t)(b * NH_ + h) * S_ + q0 + wid * 16) * D_);
            const uint32_t* qbl = (const uint32_t*)(Qlo + ((size_t)(b * NH_ + h) * S_ + q0 + wid * 16) * D_);
            uint32_t qh[8][4], ql[8][4];
#pragma unroll
            for (int f = 0; f < 8; f++) {
                int w0 = g * 64 + f * 8 + tq;
                int w1 = (g + 8) * 64 + f * 8 + tq;
                qh[f][0] = __ldcg(qbh + w0);     qh[f][1] = __ldcg(qbh + w1);
                qh[f][2] = __ldcg(qbh + w0 + 4); qh[f][3] = __ldcg(qbh + w1 + 4);
                ql[f][0] = __ldcg(qbl + w0);     ql[f][1] = __ldcg(qbl + w1);
                ql[f][2] = __ldcg(qbl + w0 + 4); ql[f][3] = __ldcg(qbl + w1 + 4);
            }

            float o[16][4];
#pragma unroll
            for (int ni = 0; ni < 16; ni++)
#pragma unroll
                for (int e = 0; e < 4; e++) o[ni][e] = 0.f;
            float m_lo = -INFINITY, m_hi = -INFINITY, l_lo = 0.f, l_hi = 0.f;

            const int qrl = q0 + wid * 16 + g;
            const int qrh = qrl + 8;

            auto do_tile = [&](const int jt, auto MASKC, const bool have_next) {
                constexpr bool MASK = decltype(MASKC)::value;
                CPWAIT0();
                __syncthreads();

                const int k0 = jt * 64;
                // dependency flags for V_jt and K_{jt+1}
                spin_flag(&g_flag[vfb + (jt >> 1)]);
                if (have_next) spin_flag(&g_flag[kfb + ((jt + 1) >> 1)]);

                // issue V_jt (single buffer)
                {
#pragma unroll
                    for (int rep = 0; rep < 4; rep++) {
                        int i = t + rep * 256;
                        int r2 = i >> 3, cc2 = i & 7;
                        uint32_t so2 = (uint32_t)((r2 * 9 + cc2) * 16);
                        CP16(sbase + VOFF +         so2, ((const uint4*)(gvh_base + k0)) + (size_t)r2 * 256 + cc2);
                        CP16(sbase + VOFF + 18432 + so2, ((const uint4*)(gvl_base + k0)) + (size_t)r2 * 256 + cc2);
                    }
                    CPCOMMIT();
                }
                if (have_next) {
                    const int kn = (jt + 1) * 64;
                    const uint32_t sb = sbase + ((jt + 1) & 1) * KBUF;
#pragma unroll
                    for (int rep = 0; rep < 4; rep++) {
                        int i = t + rep * 256;
                        int r = i >> 4, cc = i & 15;
                        uint32_t so = (uint32_t)((r * 17 + cc) * 16);
                        CP16(sb +         so, gkh + (size_t)(kn + r) * 16 + cc);
                        CP16(sb + 17408 + so, gkl + (size_t)(kn + r) * 16 + cc);
                    }
                    CPCOMMIT();
                }

                const uint32_t kb0 = sbase + (jt & 1) * KBUF;

                // --- QK^T (bf16 3-term) -> log2-domain scores ---
                float sc[8][4];
#pragma unroll
                for (int ni = 0; ni < 8; ni++)
#pragma unroll
                    for (int e = 0; e < 4; e++) sc[ni][e] = 0.f;

#pragma unroll
                for (int ks = 0; ks < 8; ks++) {
#pragma unroll
                    for (int gj = 0; gj < 4; gj++) {
                        uint32_t kb = kb0 + (uint32_t)((gj * 16 + b_row) * 272 + ks * 32 + b_coff);
                        uint32_t h0, h1, h2, h3, l0, l1, l2, l3;
                        LDSM_X4(h0, h1, h2, h3, kb);
                        LDSM_X4(l0, l1, l2, l3, kb + 17408u);
                        int ni = gj * 2;
                        MMA_BF16(sc[ni], qh[ks], h0, h1);
                        MMA_BF16(sc[ni], qh[ks], l0, l1);
                        MMA_BF16(sc[ni], ql[ks], h0, h1);
                        MMA_BF16(sc[ni + 1], qh[ks], h2, h3);
                        MMA_BF16(sc[ni + 1], qh[ks], l2, l3);
                        MMA_BF16(sc[ni + 1], ql[ks], h2, h3);
                    }
                }

                if (MASK) {
#pragma unroll
                    for (int ni = 0; ni < 8; ni++) {
#pragma unroll
                        for (int e = 0; e < 4; e++) {
                            int col = k0 + ni * 8 + tq * 2 + (e & 1);
                            int row = (e < 2) ? qrl : qrh;
                            if (col > row) sc[ni][e] = NEGBIG;
                        }
                    }
                }

                // --- online softmax (log2 domain) ---
                float mxl = NEGBIG, mxh = NEGBIG;
#pragma unroll
                for (int ni = 0; ni < 8; ni++) {
                    mxl = fmaxf(mxl, fmaxf(sc[ni][0], sc[ni][1]));
                    mxh = fmaxf(mxh, fmaxf(sc[ni][2], sc[ni][3]));
                }
                mxl = fmaxf(mxl, __shfl_xor_sync(0xffffffffu, mxl, 1));
                mxl = fmaxf(mxl, __shfl_xor_sync(0xffffffffu, mxl, 2));
                mxh = fmaxf(mxh, __shfl_xor_sync(0xffffffffu, mxh, 1));
                mxh = fmaxf(mxh, __shfl_xor_sync(0xffffffffu, mxh, 2));

                float mnl = fmaxf(m_lo, mxl), mnh = fmaxf(m_hi, mxh);
                float cl = ex2f(m_lo - mnl), chh = ex2f(m_hi - mnh);
                m_lo = mnl; m_hi = mnh;

                float sl = 0.f, sh = 0.f;
#pragma unroll
                for (int ni = 0; ni < 8; ni++) {
                    float p0 = ex2f(sc[ni][0] - mnl);
                    float p1 = ex2f(sc[ni][1] - mnl);
                    float p2 = ex2f(sc[ni][2] - mnh);
                    float p3 = ex2f(sc[ni][3] - mnh);
                    sc[ni][0] = p0; sc[ni][1] = p1; sc[ni][2] = p2; sc[ni][3] = p3;
                    sl += p0 + p1; sh += p2 + p3;
                }
                sl += __shfl_xor_sync(0xffffffffu, sl, 1);
                sl += __shfl_xor_sync(0xffffffffu, sl, 2);
                sh += __shfl_xor_sync(0xffffffffu, sh, 1);
                sh += __shfl_xor_sync(0xffffffffu, sh, 2);
                l_lo = l_lo * cl + sl;
                l_hi = l_hi * chh + sh;

#pragma unroll
                for (int ni = 0; ni < 16; ni++) {
                    o[ni][0] *= cl; o[ni][1] *= cl;
                    o[ni][2] *= chh; o[ni][3] *= chh;
                }

                uint32_t ph[4][4];
#pragma unroll
                for (int f = 0; f < 4; f++) {
                    PACK_F16(ph[f][0], sc[2 * f][0],     sc[2 * f][1]);
                    PACK_F16(ph[f][1], sc[2 * f][2],     sc[2 * f][3]);
                    PACK_F16(ph[f][2], sc[2 * f + 1][0], sc[2 * f + 1][1]);
                    PACK_F16(ph[f][3], sc[2 * f + 1][2], sc[2 * f + 1][3]);
                }

                if (have_next) { CPWAIT1(); } else { CPWAIT0(); }
                __syncthreads();

                // --- P·V (fp16 2-term) ---
#pragma unroll
                for (int f = 0; f < 4; f++) {
#pragma unroll
                    for (int gj = 0; gj < 8; gj++) {
                        uint32_t vb = sbase + VOFF + (uint32_t)((gj * 16 + b_row) * 144 + f * 32 + b_coff);
                        uint32_t h0, h1, h2, h3, l0, l1, l2, l3;
                        LDSM_X4(h0, h1, h2, h3, vb);
                        LDSM_X4(l0, l1, l2, l3, vb + 18432u);
                        int ni = gj * 2;
                        MMA_FP16(o[ni], ph[f], h0, h1);
                        MMA_FP16(o[ni], ph[f], l0, l1);
                        MMA_FP16(o[ni + 1], ph[f], h2, h3);
                        MMA_FP16(o[ni + 1], ph[f], l2, l3);
                    }
                }
            };

            for (int jt = 0; jt < ntiles - 2; jt++) do_tile(jt, FalseT{}, true);
            do_tile(ntiles - 2, TrueT{}, true);
            do_tile(ntiles - 1, TrueT{}, false);

            float invl = 1.0f / l_lo, invh = 1.0f / l_hi;
#pragma unroll
            for (int ni = 0; ni < 16; ni++) {
                int d = ni * 8 + tq * 2;
                float2 w0 = make_float2(o[ni][0] * invl, o[ni][1] * invl);
                float2 w1 = make_float2(o[ni][2] * invh, o[ni][3] * invh);
                *(float2*)(out + ((size_t)(b * S_) + qrl) * HID_ + h * 128 + d) = w0;
                *(float2*)(out + ((size_t)(b * S_) + qrh) * HID_ + h * 128 + d) = w1;
            }
        }
    }
}

// ---------------------------------------------------------------------------
extern "C" void kernel_launch(void* const* d_in, const int* in_sizes, int n_in,
                              void* d_out, int out_size)
{
    const float* hs = (const float*)d_in[0];
    const float* Wq = (const float*)d_in[1];
    const float* bq = (const float*)d_in[2];
    const float* Wk = (const float*)d_in[3];
    const float* bk = (const float*)d_in[4];
    const float* Wv = (const float*)d_in[5];
    const float* bv = (const float*)d_in[6];
    float* out = (float*)d_out;

    bf16 *ahi, *alo, *whi, *wlo;
    bf16 *qhi, *qlo, *khi, *klo;
    __half *vthi, *vtlo;
    float2* rtab;
    cudaGetSymbolAddress((void**)&ahi, g_ahi);
    cudaGetSymbolAddress((void**)&alo, g_alo);
    cudaGetSymbolAddress((void**)&whi, g_whi);
    cudaGetSymbolAddress((void**)&wlo, g_wlo);
    cudaGetSymbolAddress((void**)&qhi, g_qhi);
    cudaGetSymbolAddress((void**)&qlo, g_qlo);
    cudaGetSymbolAddress((void**)&khi, g_khi);
    cudaGetSymbolAddress((void**)&klo, g_klo);
    cudaGetSymbolAddress((void**)&vthi, g_vthi);
    cudaGetSymbolAddress((void**)&vtlo, g_vtlo);
    cudaGetSymbolAddress((void**)&rtab, g_rope);

    prep_all<<<(PREP_THREADS + 255) / 256, 256>>>(
        (const float4*)hs, (const float4*)Wq, (const float4*)Wk, (const float4*)Wv,
        (uint4*)ahi, (uint4*)alo, (uint4*)whi, (uint4*)wlo, rtab);

    cudaFuncSetAttribute(fused_hmma, cudaFuncAttributeMaxDynamicSharedMemorySize, FUSED_SMEM);
    fused_hmma<<<304, 256, FUSED_SMEM>>>(ahi, alo, whi, wlo, bq, bk, bv, rtab,
                                         qhi, qlo, khi, klo, vthi, vtlo, out);
}

// round 17
// speedup vs baseline: 1.1028x; 1.1028x over previous
#include <cuda_runtime.h>
#include <cuda_bf16.h>
#include <cuda_fp16.h>
#include <cstdint>
#include <math.h>

#define B_   2
#define S_   2048
#define HID_ 2048
#define NH_  16
#define NKV_ 4
#define D_   128
#define GK   2048

typedef __nv_bfloat16 bf16;

// ---------------------------------------------------------------------------
// Device globals
// ---------------------------------------------------------------------------
__device__ bf16 g_ahi[(size_t)B_ * S_ * HID_];
__device__ bf16 g_alo[(size_t)B_ * S_ * HID_];
// W arena rows 0..2047 = Wq, 2048..2559 = Wk, 2560..3071 = Wv
__device__ bf16 g_whi[6291456];
__device__ bf16 g_wlo[6291456];

__device__ __half g_q[(size_t)B_ * NH_ * S_ * D_];      // single fp16, qsc folded
__device__ __half g_khi[(size_t)B_ * NKV_ * S_ * D_];   // fp16 hi/lo
__device__ __half g_klo[(size_t)B_ * NKV_ * S_ * D_];
__device__ __half g_vthi[(size_t)B_ * NKV_ * D_ * S_];  // [b][kvh][d][s]
__device__ __half g_vtlo[(size_t)B_ * NKV_ * D_ * S_];

__device__ float2 g_rope[S_ * 64];
__device__ int    g_work;          // attention work-steal counter (reset in prep)

#define N_WORK 1024                // 32 iblk x 16 h x 2 b

struct FalseT { static constexpr bool value = false; };
struct TrueT  { static constexpr bool value = true;  };

// ---------------------------------------------------------------------------
// Helpers
// ---------------------------------------------------------------------------
#define MMA_BF16(C, A, b0v, b1v)                                              \
    asm volatile("mma.sync.aligned.m16n8k16.row.col.f32.bf16.bf16.f32 "       \
                 "{%0,%1,%2,%3}, {%4,%5,%6,%7}, {%8,%9}, {%0,%1,%2,%3};"      \
                 : "+f"((C)[0]), "+f"((C)[1]), "+f"((C)[2]), "+f"((C)[3])     \
                 : "r"((A)[0]), "r"((A)[1]), "r"((A)[2]), "r"((A)[3]),        \
                   "r"(b0v), "r"(b1v))

#define MMA_FP16(C, A, b0v, b1v)                                              \
    asm volatile("mma.sync.aligned.m16n8k16.row.col.f32.f16.f16.f32 "         \
                 "{%0,%1,%2,%3}, {%4,%5,%6,%7}, {%8,%9}, {%0,%1,%2,%3};"      \
                 : "+f"((C)[0]), "+f"((C)[1]), "+f"((C)[2]), "+f"((C)[3])     \
                 : "r"((A)[0]), "r"((A)[1]), "r"((A)[2]), "r"((A)[3]),        \
                   "r"(b0v), "r"(b1v))

#define LDSM_X4(R0, R1, R2, R3, ADDR)                                         \
    asm volatile("ldmatrix.sync.aligned.m8n8.x4.shared.b16 {%0,%1,%2,%3}, [%4];" \
                 : "=r"(R0), "=r"(R1), "=r"(R2), "=r"(R3) : "r"(ADDR))

#define CP16(sa, ga) \
    asm volatile("cp.async.cg.shared.global [%0], [%1], 16;" :: "r"(sa), "l"(ga) : "memory")
#define CPCOMMIT() asm volatile("cp.async.commit_group;" ::: "memory")
#define CPWAIT1()  asm volatile("cp.async.wait_group 1;" ::: "memory")
#define CPWAIT0()  asm volatile("cp.async.wait_group 0;" ::: "memory")

// pack two fp32 into f16x2: low half = xe (even col), high half = xo (odd col)
#define PACK_F16(dst, xe, xo) \
    asm("cvt.rn.f16x2.f32 %0, %1, %2;" : "=r"(dst) : "f"(xo), "f"(xe))

__device__ __forceinline__ float ex2f(float x) {
    float r;
    asm("ex2.approx.f32 %0, %1;" : "=f"(r) : "f"(x));
    return r;
}

__device__ __forceinline__ uint32_t smem_to_u32(const void* p) {
    uint32_t a;
    asm("{ .reg .u64 t; cvta.to.shared.u64 t, %1; cvt.u32.u64 %0, t; }" : "=r"(a) : "l"(p));
    return a;
}

__device__ __forceinline__ void split_pack(float xe, float xo,
                                           uint32_t& hi, uint32_t& lo) {
    bf16 he = __float2bfloat16_rn(xe);
    bf16 ho = __float2bfloat16_rn(xo);
    float re = xe - __bfloat162float(he);
    float ro = xo - __bfloat162float(ho);
    asm("cvt.rn.bf16x2.f32 %0, %1, %2;" : "=r"(hi) : "f"(__bfloat162float(ho)), "f"(__bfloat162float(he)));
    asm("cvt.rn.bf16x2.f32 %0, %1, %2;" : "=r"(lo) : "f"(ro), "f"(re));
}

// fp16 hi/lo split of a pair, packed as f16x2 words
__device__ __forceinline__ void split_pack_f16(float xe, float xo,
                                               uint32_t& hi, uint32_t& lo) {
    __half he = __float2half_rn(xe);
    __half ho = __float2half_rn(xo);
    float re = xe - __half2float(he);
    float ro = xo - __half2float(ho);
    hi = ((uint32_t)__half_as_ushort(ho) << 16) | __half_as_ushort(he);
    PACK_F16(lo, re, ro);
}

// ---------------------------------------------------------------------------
// Fused prep: splits + rope table + work-counter reset.
// ---------------------------------------------------------------------------
#define PREP_SPLIT 1835008
#define PREP_THREADS 1966080

__global__ __launch_bounds__(256) void prep_all(
    const float4* __restrict__ hs, const float4* __restrict__ Wq,
    const float4* __restrict__ Wk, const float4* __restrict__ Wv,
    uint4* __restrict__ ahi, uint4* __restrict__ alo,
    uint4* __restrict__ whi, uint4* __restrict__ wlo,
    float2* __restrict__ rtab)
{
    int i = blockIdx.x * 256 + threadIdx.x;
    if (i >= PREP_THREADS) return;
    if (i == 0) g_work = 0;

    if (i >= PREP_SPLIT) {            // rope table
        int idx = i - PREP_SPLIT;     // < 131072
        int d = idx & 63, s = idx >> 6;
        float e2   = (float)(2 * d) * (1.0f / 128.0f);
        float invf = (float)exp(-(double)e2 * 13.815510557964274);
        float ang  = (float)s * invf;
        float sn, cs;
        sincosf(ang, &sn, &cs);
        rtab[idx] = make_float2(cs, sn);
        return;
    }

    const float4* src;
    uint4 *dh, *dl;
    int j;
    if (i < 1048576)      { src = hs; j = i;           dh = ahi;          dl = alo;          }
    else if (i < 1572864) { src = Wq; j = i - 1048576; dh = whi;          dl = wlo;          }
    else if (i < 1703936) { src = Wk; j = i - 1572864; dh = whi + 524288; dl = wlo + 524288; }
    else                  { src = Wv; j = i - 1703936; dh = whi + 655360; dl = wlo + 655360; }

    float4 a = src[2 * j], b = src[2 * j + 1];
    uint32_t h[4], l[4];
    split_pack(a.x, a.y, h[0], l[0]);
    split_pack(a.z, a.w, h[1], l[1]);
    split_pack(b.x, b.y, h[2], l[2]);
    split_pack(b.z, b.w, h[3], l[3]);
    dh[j] = make_uint4(h[0], h[1], h[2], h[3]);
    dl[j] = make_uint4(l[0], l[1], l[2], l[3]);
}

// ---------------------------------------------------------------------------
// HMMA projection GEMM (Q+K+V), grid (24, 32), single-sync cp.async pipeline.
// Q: single fp16, qsc=scale*log2e folded, rope.  K: fp16 hi/lo, rope.
// V: fp16 hi/lo transposed.
// ---------------------------------------------------------------------------
#define GBUF 40960
#define GEMM_SMEM (2 * GBUF)

__global__ __launch_bounds__(256, 2) void gemm_hmma(
    const bf16* __restrict__ Ahi, const bf16* __restrict__ Alo,
    const bf16* __restrict__ WhiA, const bf16* __restrict__ WloA,
    const float* __restrict__ bq, const float* __restrict__ bk,
    const float* __restrict__ bv, const float2* __restrict__ rtab,
    __half* __restrict__ Q,
    __half* __restrict__ Khi, __half* __restrict__ Klo,
    __half* __restrict__ Vthi, __half* __restrict__ Vtlo)
{
    extern __shared__ char gsm[];
    const uint32_t sbase = smem_to_u32(gsm);

    const int t    = threadIdx.x;
    const int wid  = t >> 5;
    const int lane = t & 31;
    const int g    = lane >> 2;
    const int tq   = lane & 3;
    const int wy   = wid >> 1;
    const int wx   = wid & 1;
    const int nt   = blockIdx.x;
    const int m0   = blockIdx.y << 7;
    const int wrow0 = nt << 7;

    const int a_row  = lane & 15;
    const int a_coff = (lane >> 4) * 16;
    const int b_row  = (lane & 7) + ((lane >> 4) & 1) * 8;
    const int b_coff = ((lane >> 3) & 1) * 16;

    const float* bias_l; int n0l, Hn, mode;
    if (nt < 16)      { bias_l = bq; n0l = nt << 7;        Hn = NH_;  mode = 1; }
    else if (nt < 20) { bias_l = bk; n0l = (nt - 16) << 7; Hn = NKV_; mode = 2; }
    else              { bias_l = bv; n0l = (nt - 20) << 7; Hn = NKV_; mode = 0; }

    // Q pre-scale: scale * log2(e); K/V multiplied by exact 1.0f
    const float qsc = (mode == 1) ? (0.08838834764831845f * 1.4426950408889634f) : 1.0f;

    float c[2][8][4];
#pragma unroll
    for (int mi = 0; mi < 2; mi++)
#pragma unroll
        for (int ni = 0; ni < 8; ni++)
#pragma unroll
            for (int e = 0; e < 4; e++) c[mi][ni][e] = 0.f;

    // prefetch chunk 0
    {
        const uint32_t sb = sbase;
#pragma unroll
        for (int rep = 0; rep < 2; rep++) {
            int i = t + rep * 256;
            int r = i >> 2, cc = i & 3;
            uint32_t so = (uint32_t)((r * 40 + cc * 8) * 2);
            size_t goA = (size_t)(m0 + r) * GK + cc * 8;
            size_t goW = (size_t)(wrow0 + r) * GK + cc * 8;
            CP16(sb +     0 + so, Ahi  + goA);
            CP16(sb + 10240 + so, Alo  + goA);
            CP16(sb + 20480 + so, WhiA + goW);
            CP16(sb + 30720 + so, WloA + goW);
        }
        CPCOMMIT();
    }

    for (int ch = 0; ch < GK / 32; ch++) {
        CPWAIT0();
        __syncthreads();
        if (ch < GK / 32 - 1) {
            const int kc = (ch + 1) * 32;
            const uint32_t sb = sbase + ((ch + 1) & 1) * GBUF;
#pragma unroll
            for (int rep = 0; rep < 2; rep++) {
                int i = t + rep * 256;
                int r = i >> 2, cc = i & 3;
                uint32_t so = (uint32_t)((r * 40 + cc * 8) * 2);
                size_t goA = (size_t)(m0 + r) * GK + kc + cc * 8;
                size_t goW = (size_t)(wrow0 + r) * GK + kc + cc * 8;
                CP16(sb +     0 + so, Ahi  + goA);
                CP16(sb + 10240 + so, Alo  + goA);
                CP16(sb + 20480 + so, WhiA + goW);
                CP16(sb + 30720 + so, WloA + goW);
            }
            CPCOMMIT();
        }

        const uint32_t bufb = sbase + (ch & 1) * GBUF;

#pragma unroll
        for (int ks = 0; ks < 2; ks++) {
            uint32_t ah[2][4], al[2][4];
#pragma unroll
            for (int mi = 0; mi < 2; mi++) {
                uint32_t ra = bufb + (uint32_t)((wy * 32 + mi * 16 + a_row) * 80 + ks * 32 + a_coff);
                LDSM_X4(ah[mi][0], ah[mi][1], ah[mi][2], ah[mi][3], ra);
                LDSM_X4(al[mi][0], al[mi][1], al[mi][2], al[mi][3], ra + 10240u);
            }
#pragma unroll
            for (int gj = 0; gj < 4; gj++) {
                int n0 = wx * 32 + (gj & 1) * 16 + (gj >> 1) * 64;
                uint32_t rb = bufb + 20480u + (uint32_t)((n0 + b_row) * 80 + ks * 32 + b_coff);
                uint32_t h0, h1, h2, h3, l0, l1, l2, l3;
                LDSM_X4(h0, h1, h2, h3, rb);
                LDSM_X4(l0, l1, l2, l3, rb + 10240u);
                int ni = gj * 2;
#pragma unroll
                for (int mi = 0; mi < 2; mi++) {
                    MMA_BF16(c[mi][ni], ah[mi], h0, h1);
                    MMA_BF16(c[mi][ni], ah[mi], l0, l1);
                    MMA_BF16(c[mi][ni], al[mi], h0, h1);
                    MMA_BF16(c[mi][ni + 1], ah[mi], h2, h3);
                    MMA_BF16(c[mi][ni + 1], ah[mi], l2, l3);
                    MMA_BF16(c[mi][ni + 1], al[mi], h2, h3);
                }
            }
        }
    }

    const int h = n0l >> 7;

    if (mode != 0) {
        // Q/K: bias+rope (+qsc), stage in smem, coalesced uint4 stores.
        __syncthreads();
        uint32_t* stageh = (uint32_t*)gsm;              // 128 rows x 68 u32
        uint32_t* stagel = (uint32_t*)(gsm + 34816);
#pragma unroll
        for (int mi = 0; mi < 2; mi++) {
#pragma unroll
            for (int half = 0; half < 2; half++) {
                int srl = wy * 32 + mi * 16 + g + half * 8;
                int rr  = m0 + srl;
                int eo  = half * 2;
                int sr  = rr & (S_ - 1);
#pragma unroll
                for (int ni = 0; ni < 4; ni++) {
                    int d1 = wx * 32 + ni * 8 + tq * 2;
                    float x1a = c[mi][ni][eo]         + bias_l[n0l + d1];
                    float x1b = c[mi][ni][eo + 1]     + bias_l[n0l + d1 + 1];
                    float x2a = c[mi][ni + 4][eo]     + bias_l[n0l + d1 + 64];
                    float x2b = c[mi][ni + 4][eo + 1] + bias_l[n0l + d1 + 65];
                    float2 ca = rtab[sr * 64 + d1];
                    float2 cb = rtab[sr * 64 + d1 + 1];
                    float o1a = (x1a * ca.x - x2a * ca.y) * qsc;
                    float o2a = (x2a * ca.x + x1a * ca.y) * qsc;
                    float o1b = (x1b * cb.x - x2b * cb.y) * qsc;
                    float o2b = (x2b * cb.x + x1b * cb.y) * qsc;
                    if (mode == 1) {
                        uint32_t p1, p2;
                        PACK_F16(p1, o1a, o1b);
                        PACK_F16(p2, o2a, o2b);
                        stageh[srl * 68 + (d1 >> 1)]        = p1;
                        stageh[srl * 68 + ((d1 + 64) >> 1)] = p2;
                    } else {
                        uint32_t ph, pl;
                        split_pack_f16(o1a, o1b, ph, pl);
                        stageh[srl * 68 + (d1 >> 1)] = ph;
                        stagel[srl * 68 + (d1 >> 1)] = pl;
                        split_pack_f16(o2a, o2b, ph, pl);
                        stageh[srl * 68 + ((d1 + 64) >> 1)] = ph;
                        stagel[srl * 68 + ((d1 + 64) >> 1)] = pl;
                    }
                }
            }
        }
        __syncthreads();
        const int bb  = m0 >> 11;
        const int sr0 = m0 & (S_ - 1);
        const uint4* sh4 = (const uint4*)stageh;
        const uint4* sl4 = (const uint4*)stagel;
        if (mode == 1) {
            uint4* O4 = (uint4*)Q;
            for (int idx = t; idx < 128 * 16; idx += 256) {
                int r = idx >> 4, cc = idx & 15;
                size_t off = ((size_t)(bb * Hn + h) * S_ + sr0 + r) * 16 + cc;
                O4[off] = sh4[r * 17 + cc];
            }
        } else {
            uint4* O4h = (uint4*)Khi;
            uint4* O4l = (uint4*)Klo;
            for (int idx = t; idx < 128 * 16; idx += 256) {
                int r = idx >> 4, cc = idx & 15;
                size_t off = ((size_t)(bb * Hn + h) * S_ + sr0 + r) * 16 + cc;
                O4h[off] = sh4[r * 17 + cc];
                O4l[off] = sl4[r * 17 + cc];
            }
        }
    } else {
        // V: fp16 hi/lo, stage [d][sr], coalesced uint4 stores.
        __syncthreads();
        __half* stageh = (__half*)gsm;                 // 128 x 136
        __half* stagel = (__half*)(gsm + 34816);
#pragma unroll
        for (int mi = 0; mi < 2; mi++) {
#pragma unroll
            for (int half = 0; half < 2; half++) {
                int srl = wy * 32 + mi * 16 + g + half * 8;
                int eo = half * 2;
#pragma unroll
                for (int ni = 0; ni < 8; ni++) {
                    int d = wx * 32 + (ni & 3) * 8 + (ni >> 2) * 64 + tq * 2;
#pragma unroll
                    for (int e = 0; e < 2; e++) {
                        float x = c[mi][ni][eo + e] + bias_l[n0l + d + e];
                        __half hv = __float2half_rn(x);
                        stageh[(d + e) * 136 + srl] = hv;
                        stagel[(d + e) * 136 + srl] = __float2half_rn(x - __half2float(hv));
                    }
                }
            }
        }
        __syncthreads();
        const int bb = m0 >> 11;
        const int sr0 = m0 & (S_ - 1);
        const uint4* sh4 = (const uint4*)stageh;
        const uint4* sl4 = (const uint4*)stagel;
        for (int idx = t; idx < 128 * 16; idx += 256) {
            int r = idx >> 4, cc = idx & 15;
            uint4 vh = sh4[r * 17 + cc];
            uint4 vl = sl4[r * 17 + cc];
            size_t off = ((size_t)(bb * Hn + h) * D_ + r) * S_ + sr0 + cc * 8;
            *(uint4*)(Vthi + off) = vh;
            *(uint4*)(Vtlo + off) = vl;
        }
    }
}

// ---------------------------------------------------------------------------
// Persistent HMMA flash attention, work-steal, heavy-first, DIAG-peeled.
// Q single fp16 (qsc folded), K fp16 hi/lo -> QK = 2 fp16 MMAs.
// PV fp16 2-term. Log2-domain softmax with raw ex2.
// ---------------------------------------------------------------------------
#define KBUF 34816
#define VOFF 69632
#define ATT_SMEM 106496

__global__ __launch_bounds__(128, 2) void attn_hmma(
    const __half* __restrict__ Q,
    const __half* __restrict__ Khi, const __half* __restrict__ Klo,
    const __half* __restrict__ Vthi, const __half* __restrict__ Vtlo,
    float* __restrict__ out)
{
    extern __shared__ char asm_[];
    __shared__ int s_item;
    const uint32_t sbase = smem_to_u32(asm_);

    const int t    = threadIdx.x;
    const int wid  = t >> 5;
    const int lane = t & 31;
    const int g    = lane >> 2;
    const int tq   = lane & 3;

    const int b_row  = (lane & 7) + ((lane >> 4) & 1) * 8;
    const int b_coff = ((lane >> 3) & 1) * 16;

    const float NEGBIG = -3.402823466e38f;

    while (true) {
        __syncthreads();
        if (t == 0) s_item = atomicAdd(&g_work, 1);
        __syncthreads();
        const int w = s_item;
        if (w >= N_WORK) break;

        const int iblk = 31 - (w >> 5);
        const int h    = w & 15;
        const int b    = (w >> 4) & 1;
        const int q0   = iblk * 64;
        const int kvh  = h >> 2;

        const uint4* gkh = (const uint4*)(Khi + ((size_t)(b * NKV_ + kvh) * S_) * D_);
        const uint4* gkl = (const uint4*)(Klo + ((size_t)(b * NKV_ + kvh) * S_) * D_);
        const __half* gvh_base = Vthi + (size_t)(b * NKV_ + kvh) * D_ * S_;
        const __half* gvl_base = Vtlo + (size_t)(b * NKV_ + kvh) * D_ * S_;

        const int ntiles = iblk + 1;

        // prologue: prefetch K tile 0
        {
            const uint32_t sb = sbase;
#pragma unroll
            for (int rep = 0; rep < 8; rep++) {
                int i = t + rep * 128;
                int r = i >> 4, cc = i & 15;
                uint32_t so = (uint32_t)((r * 17 + cc) * 16);
                CP16(sb +         so, gkh + (size_t)r * 16 + cc);
                CP16(sb + 17408 + so, gkl + (size_t)r * 16 + cc);
            }
            CPCOMMIT();
        }

        // Q fragments (single fp16)
        const uint32_t* qb = (const uint32_t*)(Q + ((size_t)(b * NH_ + h) * S_ + q0 + wid * 16) * D_);
        uint32_t qh[8][4];
#pragma unroll
        for (int f = 0; f < 8; f++) {
            int w0 = g * 64 + f * 8 + tq;
            int w1 = (g + 8) * 64 + f * 8 + tq;
            qh[f][0] = qb[w0];     qh[f][1] = qb[w1];
            qh[f][2] = qb[w0 + 4]; qh[f][3] = qb[w1 + 4];
        }

        float o[16][4];
#pragma unroll
        for (int ni = 0; ni < 16; ni++)
#pragma unroll
            for (int e = 0; e < 4; e++) o[ni][e] = 0.f;
        float m_lo = -INFINITY, m_hi = -INFINITY, l_lo = 0.f, l_hi = 0.f;

        const int qrl = q0 + wid * 16 + g;
        const int qrh = qrl + 8;

        auto do_tile = [&](const int jt, auto DIAGC) {
            constexpr bool DIAG = decltype(DIAGC)::value;
            CPWAIT0();
            __syncthreads();

            const int k0 = jt * 64;
            // V_jt (single buffer)
            {
#pragma unroll
                for (int rep = 0; rep < 8; rep++) {
                    int i = t + rep * 128;
                    int r2 = i >> 3, cc2 = i & 7;
                    uint32_t so2 = (uint32_t)((r2 * 9 + cc2) * 16);
                    CP16(sbase + VOFF  +         so2, ((const uint4*)(gvh_base + k0)) + (size_t)r2 * 256 + cc2);
                    CP16(sbase + VOFF  + 18432 + so2, ((const uint4*)(gvl_base + k0)) + (size_t)r2 * 256 + cc2);
                }
                CPCOMMIT();
            }
            const bool have_next = !DIAG;   // diag tile is always last
            if (have_next) {
                const int kn = (jt + 1) * 64;
                const uint32_t sb = sbase + ((jt + 1) & 1) * KBUF;
#pragma unroll
                for (int rep = 0; rep < 8; rep++) {
                    int i = t + rep * 128;
                    int r = i >> 4, cc = i & 15;
                    uint32_t so = (uint32_t)((r * 17 + cc) * 16);
                    CP16(sb +         so, gkh + (size_t)(kn + r) * 16 + cc);
                    CP16(sb + 17408 + so, gkl + (size_t)(kn + r) * 16 + cc);
                }
                CPCOMMIT();
            }

            const uint32_t kb0 = sbase + (jt & 1) * KBUF;

            // --- QK^T (fp16 2-term: q·Khi + q·Klo) -> log2-domain scores ---
            float sc[8][4];
#pragma unroll
            for (int ni = 0; ni < 8; ni++)
#pragma unroll
                for (int e = 0; e < 4; e++) sc[ni][e] = 0.f;

#pragma unroll
            for (int ks = 0; ks < 8; ks++) {
#pragma unroll
                for (int gj = 0; gj < 4; gj++) {
                    uint32_t kb = kb0 + (uint32_t)((gj * 16 + b_row) * 272 + ks * 32 + b_coff);
                    uint32_t h0, h1, h2, h3, l0, l1, l2, l3;
                    LDSM_X4(h0, h1, h2, h3, kb);
                    LDSM_X4(l0, l1, l2, l3, kb + 17408u);
                    int ni = gj * 2;
                    MMA_FP16(sc[ni], qh[ks], h0, h1);
                    MMA_FP16(sc[ni], qh[ks], l0, l1);
                    MMA_FP16(sc[ni + 1], qh[ks], h2, h3);
                    MMA_FP16(sc[ni + 1], qh[ks], l2, l3);
                }
            }

            // causal mask only in the DIAG instantiation
            if (DIAG) {
#pragma unroll
                for (int ni = 0; ni < 8; ni++) {
#pragma unroll
                    for (int e = 0; e < 4; e++) {
                        int col = k0 + ni * 8 + tq * 2 + (e & 1);
                        int row = (e < 2) ? qrl : qrh;
                        if (col > row) sc[ni][e] = NEGBIG;
                    }
                }
            }

            // --- online softmax (log2 domain, raw ex2) ---
            float mxl = NEGBIG, mxh = NEGBIG;
#pragma unroll
            for (int ni = 0; ni < 8; ni++) {
                mxl = fmaxf(mxl, fmaxf(sc[ni][0], sc[ni][1]));
                mxh = fmaxf(mxh, fmaxf(sc[ni][2], sc[ni][3]));
            }
            mxl = fmaxf(mxl, __shfl_xor_sync(0xffffffffu, mxl, 1));
            mxl = fmaxf(mxl, __shfl_xor_sync(0xffffffffu, mxl, 2));
            mxh = fmaxf(mxh, __shfl_xor_sync(0xffffffffu, mxh, 1));
            mxh = fmaxf(mxh, __shfl_xor_sync(0xffffffffu, mxh, 2));

            float mnl = fmaxf(m_lo, mxl), mnh = fmaxf(m_hi, mxh);
            float cl = ex2f(m_lo - mnl), chh = ex2f(m_hi - mnh);
            m_lo = mnl; m_hi = mnh;

            float sl = 0.f, sh = 0.f;
#pragma unroll
            for (int ni = 0; ni < 8; ni++) {
                float p0 = ex2f(sc[ni][0] - mnl);
                float p1 = ex2f(sc[ni][1] - mnl);
                float p2 = ex2f(sc[ni][2] - mnh);
                float p3 = ex2f(sc[ni][3] - mnh);
                sc[ni][0] = p0; sc[ni][1] = p1; sc[ni][2] = p2; sc[ni][3] = p3;
                sl += p0 + p1; sh += p2 + p3;
            }
            sl += __shfl_xor_sync(0xffffffffu, sl, 1);
            sl += __shfl_xor_sync(0xffffffffu, sl, 2);
            sh += __shfl_xor_sync(0xffffffffu, sh, 1);
            sh += __shfl_xor_sync(0xffffffffu, sh, 2);
            l_lo = l_lo * cl + sl;
            l_hi = l_hi * chh + sh;

#pragma unroll
            for (int ni = 0; ni < 16; ni++) {
                o[ni][0] *= cl; o[ni][1] *= cl;
                o[ni][2] *= chh; o[ni][3] *= chh;
            }

            // --- P fragments (single fp16) ---
            uint32_t ph[4][4];
#pragma unroll
            for (int f = 0; f < 4; f++) {
                PACK_F16(ph[f][0], sc[2 * f][0],     sc[2 * f][1]);
                PACK_F16(ph[f][1], sc[2 * f][2],     sc[2 * f][3]);
                PACK_F16(ph[f][2], sc[2 * f + 1][0], sc[2 * f + 1][1]);
                PACK_F16(ph[f][3], sc[2 * f + 1][2], sc[2 * f + 1][3]);
            }

            if (have_next) { CPWAIT1(); } else { CPWAIT0(); }
            __syncthreads();

            // --- P·V (fp16 2-term) ---
#pragma unroll
            for (int f = 0; f < 4; f++) {
#pragma unroll
                for (int gj = 0; gj < 8; gj++) {
                    uint32_t vb = sbase + VOFF + (uint32_t)((gj * 16 + b_row) * 144 + f * 32 + b_coff);
                    uint32_t h0, h1, h2, h3, l0, l1, l2, l3;
                    LDSM_X4(h0, h1, h2, h3, vb);
                    LDSM_X4(l0, l1, l2, l3, vb + 18432u);
                    int ni = gj * 2;
                    MMA_FP16(o[ni], ph[f], h0, h1);
                    MMA_FP16(o[ni], ph[f], l0, l1);
                    MMA_FP16(o[ni + 1], ph[f], h2, h3);
                    MMA_FP16(o[ni + 1], ph[f], l2, l3);
                }
            }
        };

        for (int jt = 0; jt < ntiles - 1; jt++) do_tile(jt, FalseT{});
        do_tile(ntiles - 1, TrueT{});

        float invl = 1.0f / l_lo, invh = 1.0f / l_hi;
#pragma unroll
        for (int ni = 0; ni < 16; ni++) {
            int d = ni * 8 + tq * 2;
            float2 w0 = make_float2(o[ni][0] * invl, o[ni][1] * invl);
            float2 w1 = make_float2(o[ni][2] * invh, o[ni][3] * invh);
            *(float2*)(out + ((size_t)(b * S_) + qrl) * HID_ + h * 128 + d) = w0;
            *(float2*)(out + ((size_t)(b * S_) + qrh) * HID_ + h * 128 + d) = w1;
        }
    }
}

// ---------------------------------------------------------------------------
extern "C" void kernel_launch(void* const* d_in, const int* in_sizes, int n_in,
                              void* d_out, int out_size)
{
    const float* hs = (const float*)d_in[0];
    const float* Wq = (const float*)d_in[1];
    const float* bq = (const float*)d_in[2];
    const float* Wk = (const float*)d_in[3];
    const float* bk = (const float*)d_in[4];
    const float* Wv = (const float*)d_in[5];
    const float* bv = (const float*)d_in[6];
    float* out = (float*)d_out;

    bf16 *ahi, *alo, *whi, *wlo;
    __half *q, *khi, *klo, *vthi, *vtlo;
    float2* rtab;
    cudaGetSymbolAddress((void**)&ahi, g_ahi);
    cudaGetSymbolAddress((void**)&alo, g_alo);
    cudaGetSymbolAddress((void**)&whi, g_whi);
    cudaGetSymbolAddress((void**)&wlo, g_wlo);
    cudaGetSymbolAddress((void**)&q, g_q);
    cudaGetSymbolAddress((void**)&khi, g_khi);
    cudaGetSymbolAddress((void**)&klo, g_klo);
    cudaGetSymbolAddress((void**)&vthi, g_vthi);
    cudaGetSymbolAddress((void**)&vtlo, g_vtlo);
    cudaGetSymbolAddress((void**)&rtab, g_rope);

    prep_all<<<(PREP_THREADS + 255) / 256, 256>>>(
        (const float4*)hs, (const float4*)Wq, (const float4*)Wk, (const float4*)Wv,
        (uint4*)ahi, (uint4*)alo, (uint4*)whi, (uint4*)wlo, rtab);

    cudaFuncSetAttribute(gemm_hmma, cudaFuncAttributeMaxDynamicSharedMemorySize, GEMM_SMEM);
    gemm_hmma<<<dim3(24, 32), 256, GEMM_SMEM>>>(ahi, alo, whi, wlo, bq, bk, bv, rtab,
                                                q, khi, klo, vthi, vtlo);

    cudaFuncSetAttribute(attn_hmma, cudaFuncAttributeMaxDynamicSharedMemorySize, ATT_SMEM);
    attn_hmma<<<304, 128, ATT_SMEM>>>(q, khi, klo, vthi, vtlo, out);
}